// round 13
// baseline (speedup 1.0000x reference)
#include <cuda_runtime.h>
#include <cuda_bf16.h>
#include <math.h>

#define NN   1024
#define DD   256
#define HH   128
#define KSPLIT 8
#define BN_EPS 1e-5f

// ---------------- scratch (device globals; no allocation) ----------------
__device__ float g_a[NN * HH];            // X @ W1[:D] + b1
__device__ float g_c[NN * HH];            // X @ W1[D:]
__device__ float g_y[NN * HH];            // X @ Wg
__device__ float g_W[NN * NN];            // adjacency weights (symmetric, diag=1)
__device__ float g_deg[NN];               // degree (atomic accum from k2)
__device__ float g_part[KSPLIT * NN * HH];// split-K partials of W@Z
__device__ float g_raw[NN * HH];          // dis[i]*(W@Z)[i] + bg  (pre-BN)
__device__ float g_sum[HH];
__device__ float g_sumsq[HH];

// packed f32x2 helpers
#define F2LL(x) (*reinterpret_cast<unsigned long long*>(&(x)))
__device__ __forceinline__ float2 fadd2(float2 a, float2 b) {
    float2 r;
    asm("add.rn.f32x2 %0, %1, %2;" : "=l"(F2LL(r)) : "l"(F2LL(a)), "l"(F2LL(b)));
    return r;
}
__device__ __forceinline__ void ffma2(float2& acc, float2 a, float2 b) {
    asm("fma.rn.f32x2 %0, %1, %2, %0;" : "+l"(F2LL(acc)) : "l"(F2LL(a)), "l"(F2LL(b)));
}
__device__ __forceinline__ float2 pack2(float v) {
    float2 r;
    asm("mov.b64 %0, {%1, %1};" : "=l"(F2LL(r)) : "f"(v));
    return r;
}
__device__ __forceinline__ float4 ldcg4(const float* p) {
    return __ldcg((const float4*)p);
}

// ---------------- K1: direct 3x GEMM  C[1024,128] = X @ B[256,128] -------
// grid (32, 3): 32-row blocks, z selects {W1a(+b1), W1c, Wg}. Full K=256.
__global__ __launch_bounds__(256, 3)
void k1_gemm3(const float* __restrict__ X, const float* __restrict__ W1,
              const float* __restrict__ Wg, const float* __restrict__ b1) {
    const int z  = blockIdx.y;
    const int i0 = blockIdx.x * 32;
    const int t  = threadIdx.x;
    const int hq = t & 31;
    const int rq = t >> 5;
    const int h  = hq * 4;

    if (z == 0) {                       // zero accumulators used later
        if (blockIdx.x == 0) {
            if (t < 128) g_sum[t] = 0.f;
            else g_sumsq[t - 128] = 0.f;
        } else if (blockIdx.x < 5) {
            g_deg[(blockIdx.x - 1) * 256 + t] = 0.f;
        }
    }

    const float* B = (z == 0) ? W1 : (z == 1) ? (W1 + DD * HH) : Wg;

    __shared__ float Bs[32][128];
    __shared__ float Xst[32][36];

    float2 accA[4], accB[4];
    #pragma unroll
    for (int r = 0; r < 4; r++) {
        accA[r] = make_float2(0.f, 0.f);
        accB[r] = make_float2(0.f, 0.f);
    }

    #pragma unroll 1
    for (int c = 0; c < 8; c++) {
        const int k0 = c * 32;
        #pragma unroll
        for (int p = 0; p < 4; p++) {
            int pos = t * 4 + p * 1024;
            int kk = pos >> 7, hh = pos & 127;
            *(float4*)&Bs[kk][hh] = *(const float4*)&B[(k0 + kk) * HH + hh];
        }
        {
            int r = t >> 3, kkq = t & 7;
            float4 xv = *(const float4*)&X[(i0 + r) * DD + k0 + kkq * 4];
            Xst[kkq * 4 + 0][r] = xv.x;
            Xst[kkq * 4 + 1][r] = xv.y;
            Xst[kkq * 4 + 2][r] = xv.z;
            Xst[kkq * 4 + 3][r] = xv.w;
        }
        __syncthreads();
        #pragma unroll
        for (int kk = 0; kk < 32; kk++) {
            float4 b = *(const float4*)&Bs[kk][h];
            float2 b01 = make_float2(b.x, b.y);
            float2 b23 = make_float2(b.z, b.w);
            float4 x = *(const float4*)&Xst[kk][rq * 4];   // warp-uniform
            float xv[4] = {x.x, x.y, x.z, x.w};
            #pragma unroll
            for (int r = 0; r < 4; r++) {
                float2 wp = pack2(xv[r]);
                ffma2(accA[r], wp, b01);
                ffma2(accB[r], wp, b23);
            }
        }
        __syncthreads();
    }

    float bias0 = 0.f, bias1 = 0.f, bias2 = 0.f, bias3 = 0.f;
    if (z == 0) {
        float4 bv = *(const float4*)&b1[h];
        bias0 = bv.x; bias1 = bv.y; bias2 = bv.z; bias3 = bv.w;
    }
    float* dst = (z == 0) ? g_a : (z == 1) ? g_c : g_y;
    #pragma unroll
    for (int r = 0; r < 4; r++) {
        float4 v = make_float4(accA[r].x + bias0, accA[r].y + bias1,
                               accB[r].x + bias2, accB[r].y + bias3);
        *(float4*)&dst[(i0 + rq * 4 + r) * HH + h] = v;
    }
}

// ---------------- K2: pairwise sim + degree accumulation -----------------
__global__ __launch_bounds__(256, 1)
void k2_pairwise(const float* __restrict__ W2, const float* __restrict__ b2) {
    int rem = blockIdx.x;
    int ti = 0;
    #pragma unroll 1
    while (rem >= (16 - ti)) { rem -= (16 - ti); ti++; }
    const int tj = ti + rem;
    const int i0 = ti * 64, j0 = tj * 64;
    const int t = threadIdx.x;

    __shared__ float2 As2[64 * 65];
    __shared__ float2 Cs2[64 * 65];
    __shared__ float2 W2s2[64];

    if (t < 64) W2s2[t] = ((const float2*)W2)[t];
    const float2* ga2 = (const float2*)g_a;
    const float2* gc2 = (const float2*)g_c;
    #pragma unroll
    for (int p = 0; p < 16; p++) {
        int idx = t + p * 256;
        int row = idx >> 6, h2 = idx & 63;
        As2[row * 65 + h2] = ga2[(i0 + row) * 64 + h2];
        Cs2[row * 65 + h2] = gc2[(j0 + row) * 64 + h2];
    }
    __syncthreads();

    const int iq = t >> 4;
    const int jq = t & 15;

    float2 acc[4][4];
    #pragma unroll
    for (int r = 0; r < 4; r++)
        #pragma unroll
        for (int s = 0; s < 4; s++) acc[r][s] = make_float2(0.f, 0.f);

    #pragma unroll 4
    for (int h2 = 0; h2 < 64; h2++) {
        float2 w = W2s2[h2];
        float2 a[4], c[4];
        #pragma unroll
        for (int r = 0; r < 4; r++) a[r] = As2[(iq + r * 16) * 65 + h2];
        #pragma unroll
        for (int s = 0; s < 4; s++) c[s] = Cs2[(jq + s * 16) * 65 + h2];
        #pragma unroll
        for (int r = 0; r < 4; r++) {
            #pragma unroll
            for (int s = 0; s < 4; s++) {
                float2 v = fadd2(a[r], c[s]);
                v.x = fmaxf(v.x, 0.f);
                v.y = fmaxf(v.y, 0.f);
                ffma2(acc[r][s], v, w);
            }
        }
    }

    __syncthreads();
    float* Ts = (float*)As2;        // staged tile [64][68]
    const float b2v = b2[0];
    const bool diag = (ti == tj);
    #pragma unroll
    for (int r = 0; r < 4; r++) {
        #pragma unroll
        for (int s = 0; s < 4; s++) {
            int il = iq + r * 16;
            int jl = jq + s * 16;
            float x = acc[r][s].x + acc[r][s].y + b2v;
            float sg = 1.f / (1.f + __expf(-x));
            float w = (x > 0.f) ? sg : 0.f;
            if (!diag) {
                Ts[il * 68 + jl] = w;
            } else {
                if (il < jl) {
                    Ts[il * 68 + jl] = w;
                    Ts[jl * 68 + il] = w;
                } else if (il == jl) {
                    Ts[il * 68 + il] = 1.0f;
                }
            }
        }
    }
    __syncthreads();

    #pragma unroll
    for (int p = 0; p < 4; p++) {
        int idx = t + p * 256;
        int row = idx >> 4, c4 = idx & 15;
        float4 v = *(const float4*)&Ts[row * 68 + c4 * 4];
        *(float4*)&g_W[(i0 + row) * NN + j0 + c4 * 4] = v;
        float s = (v.x + v.y) + (v.z + v.w);
        #pragma unroll
        for (int o = 8; o > 0; o >>= 1) s += __shfl_down_sync(0xffffffffu, s, o, 16);
        if (c4 == 0) atomicAdd(&g_deg[i0 + row], s);
    }
    if (!diag) {
        #pragma unroll
        for (int p = 0; p < 4; p++) {
            int idx = t + p * 256;
            int jr = idx >> 4, c4 = idx & 15;
            float4 v;
            v.x = Ts[(c4 * 4 + 0) * 68 + jr];
            v.y = Ts[(c4 * 4 + 1) * 68 + jr];
            v.z = Ts[(c4 * 4 + 2) * 68 + jr];
            v.w = Ts[(c4 * 4 + 3) * 68 + jr];
            *(float4*)&g_W[(j0 + jr) * NN + i0 + c4 * 4] = v;
            float s = (v.x + v.y) + (v.z + v.w);
            #pragma unroll
            for (int o = 8; o > 0; o >>= 1) s += __shfl_down_sync(0xffffffffu, s, o, 16);
            if (c4 == 0) atomicAdd(&g_deg[j0 + jr], s);
        }
    }
}

// ---------------- K4: split-K partials of W @ Z, 32-row blocks -----------
// grid (32, KSPLIT) = 256 blocks (>148 SMs -> ~2 CTAs/SM, 4 warps/SMSP).
// 256 threads: hq=t&31 -> h=hq*4, rq=t>>5 -> rows rq*4..+3 (warp-uniform W).
__global__ __launch_bounds__(256, 4)
void k4_aggregate() {
    const int i0 = blockIdx.x * 32;
    const int ks = blockIdx.y;
    const int t  = threadIdx.x;
    const int hq = t & 31;
    const int rq = t >> 5;
    const int h  = hq * 4;

    __shared__ float Zs[32][128];   // 16 KB
    __shared__ float Wst[32][36];   // [kk][row], 16B-aligned rows

    float2 accA[4], accB[4];
    #pragma unroll
    for (int r = 0; r < 4; r++) {
        accA[r] = make_float2(0.f, 0.f);
        accB[r] = make_float2(0.f, 0.f);
    }

    #pragma unroll 1
    for (int c = 0; c < 4; c++) {
        const int k0 = ks * 128 + c * 32;
        #pragma unroll
        for (int p = 0; p < 4; p++) {
            int pos = t * 4 + p * 1024;
            int kk = pos >> 7, hh = pos & 127;
            float dis = rsqrtf(__ldcg(&g_deg[k0 + kk]));
            float4 y = ldcg4(&g_y[(k0 + kk) * HH + hh]);
            y.x *= dis; y.y *= dis; y.z *= dis; y.w *= dis;
            *(float4*)&Zs[kk][hh] = y;
        }
        {
            int r = t >> 3, kq = t & 7;
            float4 wv = ldcg4(&g_W[(i0 + r) * NN + k0 + kq * 4]);
            Wst[kq * 4 + 0][r] = wv.x;
            Wst[kq * 4 + 1][r] = wv.y;
            Wst[kq * 4 + 2][r] = wv.z;
            Wst[kq * 4 + 3][r] = wv.w;
        }
        __syncthreads();
        #pragma unroll
        for (int kk = 0; kk < 32; kk++) {
            float4 zv = *(const float4*)&Zs[kk][h];
            float2 z01 = make_float2(zv.x, zv.y);
            float2 z23 = make_float2(zv.z, zv.w);
            float4 wa = *(const float4*)&Wst[kk][rq * 4];  // warp-uniform bcast
            float wv4[4] = {wa.x, wa.y, wa.z, wa.w};
            #pragma unroll
            for (int r = 0; r < 4; r++) {
                float2 wp = pack2(wv4[r]);
                ffma2(accA[r], wp, z01);
                ffma2(accB[r], wp, z23);
            }
        }
        __syncthreads();
    }

    #pragma unroll
    for (int r = 0; r < 4; r++) {
        float4 v = make_float4(accA[r].x, accA[r].y, accB[r].x, accB[r].y);
        *(float4*)&g_part[(ks * NN + i0 + rq * 4 + r) * HH + h] = v;
    }
}

// ---------------- K5: reduce partials (8x LDG.128) + epilogue + stats ----
// grid 128: 8 rows/block, 32 threads per row, float4 per thread.
// BN stats staged through smem -> 256 global atomics per block.
__global__ __launch_bounds__(256, 4)
void k5_stats(const float* __restrict__ bg) {
    const int t = threadIdx.x;
    const int rr = t >> 5;            // 0..7 row within block
    const int hq = t & 31;
    const int h  = hq * 4;
    const int i  = blockIdx.x * 8 + rr;
    const int idx = i * HH + h;

    float4 p[KSPLIT];
    #pragma unroll
    for (int ks = 0; ks < KSPLIT; ks++)
        p[ks] = ldcg4(&g_part[ks * NN * HH + idx]);
    float dis = rsqrtf(__ldcg(&g_deg[i]));
    float4 bgv = *(const float4*)&bg[h];

    float4 acc;
    acc.x = ((p[0].x + p[1].x) + (p[2].x + p[3].x)) + ((p[4].x + p[5].x) + (p[6].x + p[7].x));
    acc.y = ((p[0].y + p[1].y) + (p[2].y + p[3].y)) + ((p[4].y + p[5].y) + (p[6].y + p[7].y));
    acc.z = ((p[0].z + p[1].z) + (p[2].z + p[3].z)) + ((p[4].z + p[5].z) + (p[6].z + p[7].z));
    acc.w = ((p[0].w + p[1].w) + (p[2].w + p[3].w)) + ((p[4].w + p[5].w) + (p[6].w + p[7].w));

    float4 v = make_float4(acc.x * dis + bgv.x, acc.y * dis + bgv.y,
                           acc.z * dis + bgv.z, acc.w * dis + bgv.w);
    *(float4*)&g_raw[idx] = v;

    __shared__ float redS[8 * 132];
    __shared__ float redQ[8 * 132];
    *(float4*)&redS[rr * 132 + h] = v;
    *(float4*)&redQ[rr * 132 + h] = make_float4(v.x * v.x, v.y * v.y,
                                                v.z * v.z, v.w * v.w);
    __syncthreads();
    if (t < 128) {
        float s = 0.f, q = 0.f;
        #pragma unroll
        for (int r = 0; r < 8; r++) {
            s += redS[r * 132 + t];
            q += redQ[r * 132 + t];
        }
        atomicAdd(&g_sum[t], s);
        atomicAdd(&g_sumsq[t], q);
    }
}

// ---------------- K6: normalize + relu -> d_out (float4) -----------------
__global__ __launch_bounds__(256, 4)
void k6_norm(const float* __restrict__ gamma, const float* __restrict__ beta,
             float* __restrict__ out) {
    const int idx = blockIdx.x * 256 + threadIdx.x;   // float4 idx 0..32767
    const int h4 = (idx & 31) * 4;
    const float inv_n = 1.f / (float)NN;
    float4 sm = *(const float4*)&g_sum[h4];
    float4 sq = *(const float4*)&g_sumsq[h4];
    float4 gm = *(const float4*)&gamma[h4];
    float4 bt = *(const float4*)&beta[h4];
    float4 x = ((const float4*)g_raw)[idx];
    float m, vv, sc;
    m = sm.x * inv_n; vv = sq.x * inv_n - m * m; sc = gm.x * rsqrtf(vv + BN_EPS);
    x.x = fmaxf((x.x - m) * sc + bt.x, 0.f);
    m = sm.y * inv_n; vv = sq.y * inv_n - m * m; sc = gm.y * rsqrtf(vv + BN_EPS);
    x.y = fmaxf((x.y - m) * sc + bt.y, 0.f);
    m = sm.z * inv_n; vv = sq.z * inv_n - m * m; sc = gm.z * rsqrtf(vv + BN_EPS);
    x.z = fmaxf((x.z - m) * sc + bt.z, 0.f);
    m = sm.w * inv_n; vv = sq.w * inv_n - m * m; sc = gm.w * rsqrtf(vv + BN_EPS);
    x.w = fmaxf((x.w - m) * sc + bt.w, 0.f);
    ((float4*)out)[idx] = x;
}

// ---------------- launch -------------------------------------------------
extern "C" void kernel_launch(void* const* d_in, const int* in_sizes, int n_in,
                              void* d_out, int out_size) {
    const float* X     = (const float*)d_in[0];
    const float* W1    = (const float*)d_in[1];
    const float* b1    = (const float*)d_in[2];
    const float* W2    = (const float*)d_in[3];
    const float* b2    = (const float*)d_in[4];
    const float* Wg    = (const float*)d_in[5];
    const float* bg    = (const float*)d_in[6];
    const float* gamma = (const float*)d_in[7];
    const float* beta  = (const float*)d_in[8];
    float* out = (float*)d_out;

    k1_gemm3<<<dim3(32, 3), 256>>>(X, W1, Wg, b1);
    k2_pairwise<<<136, 256>>>(W2, b2);
    k4_aggregate<<<dim3(32, KSPLIT), 256>>>();
    k5_stats<<<128, 256>>>(bg);
    k6_norm<<<128, 256>>>(gamma, beta, out);
}

// round 14
// speedup vs baseline: 1.1113x; 1.1113x over previous
#include <cuda_runtime.h>
#include <cuda_bf16.h>
#include <math.h>

#define NN   1024
#define DD   256
#define HH   128
#define KSPLIT 8
#define BN_EPS 1e-5f

// ---------------- scratch (device globals; no allocation) ----------------
__device__ float g_a[NN * HH];            // X @ W1[:D] + b1
__device__ float g_c[NN * HH];            // X @ W1[D:]
__device__ float g_y[NN * HH];            // X @ Wg
__device__ float g_W[NN * NN];            // adjacency weights (symmetric, diag=1)
__device__ float g_deg[NN];               // degree (atomic accum from k2)
__device__ float g_part[KSPLIT * NN * HH];// split-K partials of W@Z
__device__ float g_raw[NN * HH];          // dis[i]*(W@Z)[i] + bg  (pre-BN)
__device__ float g_sum[HH];
__device__ float g_sumsq[HH];

// packed f32x2 helpers
#define F2LL(x) (*reinterpret_cast<unsigned long long*>(&(x)))
__device__ __forceinline__ float2 fadd2(float2 a, float2 b) {
    float2 r;
    asm("add.rn.f32x2 %0, %1, %2;" : "=l"(F2LL(r)) : "l"(F2LL(a)), "l"(F2LL(b)));
    return r;
}
__device__ __forceinline__ void ffma2(float2& acc, float2 a, float2 b) {
    asm("fma.rn.f32x2 %0, %1, %2, %0;" : "+l"(F2LL(acc)) : "l"(F2LL(a)), "l"(F2LL(b)));
}
__device__ __forceinline__ float2 pack2(float v) {
    float2 r;
    asm("mov.b64 %0, {%1, %1};" : "=l"(F2LL(r)) : "f"(v));
    return r;
}
__device__ __forceinline__ float4 ldcg4(const float* p) {
    return __ldcg((const float4*)p);
}

// ---------------- K1: direct 3x GEMM  C[1024,128] = X @ B[256,128] -------
// grid (32, 3): 32-row blocks, z selects {W1a(+b1), W1c, Wg}. Full K=256.
__global__ __launch_bounds__(256, 3)
void k1_gemm3(const float* __restrict__ X, const float* __restrict__ W1,
              const float* __restrict__ Wg, const float* __restrict__ b1) {
    const int z  = blockIdx.y;
    const int i0 = blockIdx.x * 32;
    const int t  = threadIdx.x;
    const int hq = t & 31;
    const int rq = t >> 5;
    const int h  = hq * 4;

    if (z == 0) {                       // zero accumulators used later
        if (blockIdx.x == 0) {
            if (t < 128) g_sum[t] = 0.f;
            else g_sumsq[t - 128] = 0.f;
        } else if (blockIdx.x < 5) {
            g_deg[(blockIdx.x - 1) * 256 + t] = 0.f;
        }
    }

    const float* B = (z == 0) ? W1 : (z == 1) ? (W1 + DD * HH) : Wg;

    __shared__ float Bs[32][128];
    __shared__ float Xst[32][36];

    float2 accA[4], accB[4];
    #pragma unroll
    for (int r = 0; r < 4; r++) {
        accA[r] = make_float2(0.f, 0.f);
        accB[r] = make_float2(0.f, 0.f);
    }

    #pragma unroll 1
    for (int c = 0; c < 8; c++) {
        const int k0 = c * 32;
        #pragma unroll
        for (int p = 0; p < 4; p++) {
            int pos = t * 4 + p * 1024;
            int kk = pos >> 7, hh = pos & 127;
            *(float4*)&Bs[kk][hh] = *(const float4*)&B[(k0 + kk) * HH + hh];
        }
        {
            int r = t >> 3, kkq = t & 7;
            float4 xv = *(const float4*)&X[(i0 + r) * DD + k0 + kkq * 4];
            Xst[kkq * 4 + 0][r] = xv.x;
            Xst[kkq * 4 + 1][r] = xv.y;
            Xst[kkq * 4 + 2][r] = xv.z;
            Xst[kkq * 4 + 3][r] = xv.w;
        }
        __syncthreads();
        #pragma unroll
        for (int kk = 0; kk < 32; kk++) {
            float4 b = *(const float4*)&Bs[kk][h];
            float2 b01 = make_float2(b.x, b.y);
            float2 b23 = make_float2(b.z, b.w);
            float4 x = *(const float4*)&Xst[kk][rq * 4];   // warp-uniform
            float xv[4] = {x.x, x.y, x.z, x.w};
            #pragma unroll
            for (int r = 0; r < 4; r++) {
                float2 wp = pack2(xv[r]);
                ffma2(accA[r], wp, b01);
                ffma2(accB[r], wp, b23);
            }
        }
        __syncthreads();
    }

    float bias0 = 0.f, bias1 = 0.f, bias2 = 0.f, bias3 = 0.f;
    if (z == 0) {
        float4 bv = *(const float4*)&b1[h];
        bias0 = bv.x; bias1 = bv.y; bias2 = bv.z; bias3 = bv.w;
    }
    float* dst = (z == 0) ? g_a : (z == 1) ? g_c : g_y;
    #pragma unroll
    for (int r = 0; r < 4; r++) {
        float4 v = make_float4(accA[r].x + bias0, accA[r].y + bias1,
                               accB[r].x + bias2, accB[r].y + bias3);
        *(float4*)&dst[(i0 + rq * 4 + r) * HH + h] = v;
    }
}

// ---------------- K2: pairwise sim + degree accumulation (PDL) -----------
__global__ __launch_bounds__(256, 1)
void k2_pairwise(const float* __restrict__ W2, const float* __restrict__ b2) {
    int rem = blockIdx.x;
    int ti = 0;
    #pragma unroll 1
    while (rem >= (16 - ti)) { rem -= (16 - ti); ti++; }
    const int tj = ti + rem;
    const int i0 = ti * 64, j0 = tj * 64;
    const int t = threadIdx.x;

    __shared__ float2 As2[64 * 65];
    __shared__ float2 Cs2[64 * 65];
    __shared__ float2 W2s2[64];

    if (t < 64) W2s2[t] = ((const float2*)W2)[t];     // pure input: pre-sync
    const float b2v = b2[0];                          // pure input: pre-sync

    cudaGridDependencySynchronize();                  // wait for k1's g_a/g_c

    const float2* ga2 = (const float2*)g_a;
    const float2* gc2 = (const float2*)g_c;
    #pragma unroll
    for (int p = 0; p < 16; p++) {
        int idx = t + p * 256;
        int row = idx >> 6, h2 = idx & 63;
        As2[row * 65 + h2] = ga2[(i0 + row) * 64 + h2];
        Cs2[row * 65 + h2] = gc2[(j0 + row) * 64 + h2];
    }
    __syncthreads();

    const int iq = t >> 4;
    const int jq = t & 15;

    float2 acc[4][4];
    #pragma unroll
    for (int r = 0; r < 4; r++)
        #pragma unroll
        for (int s = 0; s < 4; s++) acc[r][s] = make_float2(0.f, 0.f);

    #pragma unroll 4
    for (int h2 = 0; h2 < 64; h2++) {
        float2 w = W2s2[h2];
        float2 a[4], c[4];
        #pragma unroll
        for (int r = 0; r < 4; r++) a[r] = As2[(iq + r * 16) * 65 + h2];
        #pragma unroll
        for (int s = 0; s < 4; s++) c[s] = Cs2[(jq + s * 16) * 65 + h2];
        #pragma unroll
        for (int r = 0; r < 4; r++) {
            #pragma unroll
            for (int s = 0; s < 4; s++) {
                float2 v = fadd2(a[r], c[s]);
                v.x = fmaxf(v.x, 0.f);
                v.y = fmaxf(v.y, 0.f);
                ffma2(acc[r][s], v, w);
            }
        }
    }

    __syncthreads();
    float* Ts = (float*)As2;        // staged tile [64][68]
    const bool diag = (ti == tj);
    #pragma unroll
    for (int r = 0; r < 4; r++) {
        #pragma unroll
        for (int s = 0; s < 4; s++) {
            int il = iq + r * 16;
            int jl = jq + s * 16;
            float x = acc[r][s].x + acc[r][s].y + b2v;
            float sg = 1.f / (1.f + __expf(-x));
            float w = (x > 0.f) ? sg : 0.f;
            if (!diag) {
                Ts[il * 68 + jl] = w;
            } else {
                if (il < jl) {
                    Ts[il * 68 + jl] = w;
                    Ts[jl * 68 + il] = w;
                } else if (il == jl) {
                    Ts[il * 68 + il] = 1.0f;
                }
            }
        }
    }
    __syncthreads();

    #pragma unroll
    for (int p = 0; p < 4; p++) {
        int idx = t + p * 256;
        int row = idx >> 4, c4 = idx & 15;
        float4 v = *(const float4*)&Ts[row * 68 + c4 * 4];
        *(float4*)&g_W[(i0 + row) * NN + j0 + c4 * 4] = v;
        float s = (v.x + v.y) + (v.z + v.w);
        #pragma unroll
        for (int o = 8; o > 0; o >>= 1) s += __shfl_down_sync(0xffffffffu, s, o, 16);
        if (c4 == 0) atomicAdd(&g_deg[i0 + row], s);
    }
    if (!diag) {
        #pragma unroll
        for (int p = 0; p < 4; p++) {
            int idx = t + p * 256;
            int jr = idx >> 4, c4 = idx & 15;
            float4 v;
            v.x = Ts[(c4 * 4 + 0) * 68 + jr];
            v.y = Ts[(c4 * 4 + 1) * 68 + jr];
            v.z = Ts[(c4 * 4 + 2) * 68 + jr];
            v.w = Ts[(c4 * 4 + 3) * 68 + jr];
            *(float4*)&g_W[(j0 + jr) * NN + i0 + c4 * 4] = v;
            float s = (v.x + v.y) + (v.z + v.w);
            #pragma unroll
            for (int o = 8; o > 0; o >>= 1) s += __shfl_down_sync(0xffffffffu, s, o, 16);
            if (c4 == 0) atomicAdd(&g_deg[j0 + jr], s);
        }
    }
}

// ---------------- K4: split-K partials of W @ Z (PDL) --------------------
// grid (16, KSPLIT): 64-row blocks, k-range 128 (4 x BK=32).
__global__ __launch_bounds__(256, 3)
void k4_aggregate() {
    const int i0 = blockIdx.x * 64;
    const int ks = blockIdx.y;
    const int t  = threadIdx.x;
    const int hq = t & 31;
    const int rq = t >> 5;
    const int h  = hq * 4;

    __shared__ float Zs[32][128];
    __shared__ float Wst[32][68];

    float2 accA[8], accB[8];
    #pragma unroll
    for (int r = 0; r < 8; r++) {
        accA[r] = make_float2(0.f, 0.f);
        accB[r] = make_float2(0.f, 0.f);
    }

    cudaGridDependencySynchronize();                  // wait for k2's g_W/g_deg

    #pragma unroll 1
    for (int c = 0; c < 4; c++) {
        const int k0 = ks * 128 + c * 32;
        #pragma unroll
        for (int p = 0; p < 4; p++) {
            int pos = t * 4 + p * 1024;
            int kk = pos >> 7, hh = pos & 127;
            float dis = rsqrtf(__ldcg(&g_deg[k0 + kk]));
            float4 y = ldcg4(&g_y[(k0 + kk) * HH + hh]);
            y.x *= dis; y.y *= dis; y.z *= dis; y.w *= dis;
            *(float4*)&Zs[kk][hh] = y;
        }
        #pragma unroll
        for (int p = 0; p < 2; p++) {
            int r = (t >> 3) + p * 32;
            int kkq = t & 7;
            float4 wv = ldcg4(&g_W[(i0 + r) * NN + k0 + kkq * 4]);
            Wst[kkq * 4 + 0][r] = wv.x;
            Wst[kkq * 4 + 1][r] = wv.y;
            Wst[kkq * 4 + 2][r] = wv.z;
            Wst[kkq * 4 + 3][r] = wv.w;
        }
        __syncthreads();
        #pragma unroll
        for (int kk = 0; kk < 32; kk++) {
            float4 zv = *(const float4*)&Zs[kk][h];
            float2 z01 = make_float2(zv.x, zv.y);
            float2 z23 = make_float2(zv.z, zv.w);
            float4 wa = *(const float4*)&Wst[kk][rq * 8];      // broadcast
            float4 wb = *(const float4*)&Wst[kk][rq * 8 + 4];  // broadcast
            float wv[8] = {wa.x, wa.y, wa.z, wa.w, wb.x, wb.y, wb.z, wb.w};
            #pragma unroll
            for (int r = 0; r < 8; r++) {
                float2 wp = pack2(wv[r]);
                ffma2(accA[r], wp, z01);
                ffma2(accB[r], wp, z23);
            }
        }
        __syncthreads();
    }

    #pragma unroll
    for (int r = 0; r < 8; r++) {
        float4 v = make_float4(accA[r].x, accA[r].y, accB[r].x, accB[r].y);
        *(float4*)&g_part[(ks * NN + i0 + rq * 8 + r) * HH + h] = v;
    }
}

// ---------------- K5: reduce partials (8x LDG.128) + epilogue + stats ----
__global__ __launch_bounds__(256, 4)
void k5_stats(const float* __restrict__ bg) {
    const int t = threadIdx.x;
    const int rr = t >> 5;            // 0..7 row within block
    const int hq = t & 31;
    const int h  = hq * 4;
    const int i  = blockIdx.x * 8 + rr;
    const int idx = i * HH + h;

    float4 bgv = *(const float4*)&bg[h];              // pure input: pre-sync

    cudaGridDependencySynchronize();                  // wait for k4's g_part

    float4 p[KSPLIT];
    #pragma unroll
    for (int ks = 0; ks < KSPLIT; ks++)
        p[ks] = ldcg4(&g_part[ks * NN * HH + idx]);
    float dis = rsqrtf(__ldcg(&g_deg[i]));

    float4 acc;
    acc.x = ((p[0].x + p[1].x) + (p[2].x + p[3].x)) + ((p[4].x + p[5].x) + (p[6].x + p[7].x));
    acc.y = ((p[0].y + p[1].y) + (p[2].y + p[3].y)) + ((p[4].y + p[5].y) + (p[6].y + p[7].y));
    acc.z = ((p[0].z + p[1].z) + (p[2].z + p[3].z)) + ((p[4].z + p[5].z) + (p[6].z + p[7].z));
    acc.w = ((p[0].w + p[1].w) + (p[2].w + p[3].w)) + ((p[4].w + p[5].w) + (p[6].w + p[7].w));

    float4 v = make_float4(acc.x * dis + bgv.x, acc.y * dis + bgv.y,
                           acc.z * dis + bgv.z, acc.w * dis + bgv.w);
    *(float4*)&g_raw[idx] = v;

    __shared__ float redS[8 * 132];
    __shared__ float redQ[8 * 132];
    *(float4*)&redS[rr * 132 + h] = v;
    *(float4*)&redQ[rr * 132 + h] = make_float4(v.x * v.x, v.y * v.y,
                                                v.z * v.z, v.w * v.w);
    __syncthreads();
    if (t < 128) {
        float s = 0.f, q = 0.f;
        #pragma unroll
        for (int r = 0; r < 8; r++) {
            s += redS[r * 132 + t];
            q += redQ[r * 132 + t];
        }
        atomicAdd(&g_sum[t], s);
        atomicAdd(&g_sumsq[t], q);
    }
}

// ---------------- K6: normalize + relu -> d_out (float4, PDL) ------------
__global__ __launch_bounds__(256, 4)
void k6_norm(const float* __restrict__ gamma, const float* __restrict__ beta,
             float* __restrict__ out) {
    const int idx = blockIdx.x * 256 + threadIdx.x;   // float4 idx 0..32767
    const int h4 = (idx & 31) * 4;
    const float inv_n = 1.f / (float)NN;
    float4 gm = *(const float4*)&gamma[h4];           // pure input: pre-sync
    float4 bt = *(const float4*)&beta[h4];            // pure input: pre-sync

    cudaGridDependencySynchronize();                  // wait for k5

    float4 sm = *(const float4*)&g_sum[h4];
    float4 sq = *(const float4*)&g_sumsq[h4];
    float4 x = ((const float4*)g_raw)[idx];
    float m, vv, sc;
    m = sm.x * inv_n; vv = sq.x * inv_n - m * m; sc = gm.x * rsqrtf(vv + BN_EPS);
    x.x = fmaxf((x.x - m) * sc + bt.x, 0.f);
    m = sm.y * inv_n; vv = sq.y * inv_n - m * m; sc = gm.y * rsqrtf(vv + BN_EPS);
    x.y = fmaxf((x.y - m) * sc + bt.y, 0.f);
    m = sm.z * inv_n; vv = sq.z * inv_n - m * m; sc = gm.z * rsqrtf(vv + BN_EPS);
    x.z = fmaxf((x.z - m) * sc + bt.z, 0.f);
    m = sm.w * inv_n; vv = sq.w * inv_n - m * m; sc = gm.w * rsqrtf(vv + BN_EPS);
    x.w = fmaxf((x.w - m) * sc + bt.w, 0.f);
    ((float4*)out)[idx] = x;
}

// ---------------- launch (PDL chain) -------------------------------------
template <typename... Args>
static inline void launch_pdl(void (*kern)(Args...), dim3 grid, dim3 block,
                              Args... args) {
    cudaLaunchConfig_t cfg = {};
    cfg.gridDim = grid;
    cfg.blockDim = block;
    cudaLaunchAttribute attr[1];
    attr[0].id = cudaLaunchAttributeProgrammaticStreamSerialization;
    attr[0].val.programmaticStreamSerializationAllowed = 1;
    cfg.attrs = attr;
    cfg.numAttrs = 1;
    cudaLaunchKernelEx(&cfg, kern, args...);
}

extern "C" void kernel_launch(void* const* d_in, const int* in_sizes, int n_in,
                              void* d_out, int out_size) {
    const float* X     = (const float*)d_in[0];
    const float* W1    = (const float*)d_in[1];
    const float* b1    = (const float*)d_in[2];
    const float* W2    = (const float*)d_in[3];
    const float* b2    = (const float*)d_in[4];
    const float* Wg    = (const float*)d_in[5];
    const float* bg    = (const float*)d_in[6];
    const float* gamma = (const float*)d_in[7];
    const float* beta  = (const float*)d_in[8];
    float* out = (float*)d_out;

    k1_gemm3<<<dim3(32, 3), 256>>>(X, W1, Wg, b1);
    launch_pdl(k2_pairwise, dim3(136), dim3(256), W2, b2);
    launch_pdl(k4_aggregate, dim3(16, KSPLIT), dim3(256));
    launch_pdl(k5_stats, dim3(128), dim3(256), bg);
    launch_pdl(k6_norm, dim3(128), dim3(256), gamma, beta, out);
}